// round 13
// baseline (speedup 1.0000x reference)
#include <cuda_runtime.h>
#include <cuda_bf16.h>
#include <cstdint>

// ---------------- problem constants ----------------
#define BATCH 8192
#define DIM   256
#define TGT   16384
#define ROWS_CTA 256
#define NRB   (BATCH / ROWS_CTA)          // 32 row-blocks
#define NCT   (TGT / 128)                 // 128 col-tiles
#define NWORK (NRB * NCT)                 // 4096 work units
#define WPC   27                          // tiles per CTA (contiguous)
#define GRID_G 152                        // GB300: 152 SMs, one wave
#define SCALE_A  28.8539008177792681f     // (1/0.05) * log2(e)
#define LN2_D    0.69314718055994530942

// Padded operand-image strides
#define A_STRIDE 528                       // 512 B data + 16 skew
#define B_STRIDE 528                       // 512 B data + 16 skew (full K per row)
#define A_BLOCK  (ROWS_CTA * A_STRIDE)     // 135168
#define B_BLOCK  (64 * B_STRIDE)           // 33792 per (tile, col-half)

// ---------------- scratch (device globals; pre-padded images) ----------------
__device__ __align__(1024) uint8_t g_an[NRB * A_BLOCK];
__device__ __align__(1024) uint8_t g_tn[NCT * 2 * B_BLOCK];
__device__ float  g_diag[BATCH];
__device__ float  g_ps[16 * BATCH];
__device__ double g_loss = 0.0;
__device__ unsigned g_tick = 0;
__device__ unsigned g_done = 0;

// ---------------- helpers ----------------
__device__ __forceinline__ uint32_t smem_u32(const void* p) {
    uint32_t a;
    asm("{ .reg .u64 t; cvta.to.shared.u64 t, %1; cvt.u32.u64 %0, t; }" : "=r"(a) : "l"(p));
    return a;
}
__device__ __forceinline__ float ex2f(float x) {
    float y; asm("ex2.approx.f32 %0, %1;" : "=f"(y) : "f"(x)); return y;
}
__device__ __forceinline__ uint2 bf16x4(float4 v, float s) {
    uint2 r;
    __nv_bfloat162 lo = __floats2bfloat162_rn(v.x * s, v.y * s);
    __nv_bfloat162 hi = __floats2bfloat162_rn(v.z * s, v.w * s);
    r.x = *(uint32_t*)&lo; r.y = *(uint32_t*)&hi;
    return r;
}
__device__ __forceinline__ void ldsm_x4(uint32_t* r, uint32_t addr) {
    asm volatile("ldmatrix.sync.aligned.m8n8.x4.shared.b16 {%0,%1,%2,%3}, [%4];"
        : "=r"(r[0]), "=r"(r[1]), "=r"(r[2]), "=r"(r[3]) : "r"(addr));
}
__device__ __forceinline__ void mma16816(float* d, const uint32_t* a, const uint32_t* b) {
    asm volatile("mma.sync.aligned.m16n8k16.row.col.f32.bf16.bf16.f32 "
        "{%0,%1,%2,%3}, {%4,%5,%6,%7}, {%8,%9}, {%0,%1,%2,%3};"
        : "+f"(d[0]), "+f"(d[1]), "+f"(d[2]), "+f"(d[3])
        : "r"(a[0]), "r"(a[1]), "r"(a[2]), "r"(a[3]), "r"(b[0]), "r"(b[1]));
}
__device__ __forceinline__ void bulk_g2s(uint32_t dst, const void* src,
                                         uint32_t bytes, uint32_t mbar) {
    asm volatile("cp.async.bulk.shared::cluster.global.mbarrier::complete_tx::bytes "
                 "[%0], [%1], %2, [%3];"
                 :: "r"(dst), "l"(src), "r"(bytes), "r"(mbar) : "memory");
}
#define MBAR_INIT(a, c) asm volatile("mbarrier.init.shared.b64 [%0], %1;" :: "r"(a), "r"((uint32_t)(c)) : "memory")
#define MBAR_ARRIVE(a)  asm volatile("mbarrier.arrive.shared.b64 _, [%0];" :: "r"(a) : "memory")
#define MBAR_ARRIVE_TX(a, tx) asm volatile("mbarrier.arrive.expect_tx.shared.b64 _, [%0], %1;" :: "r"(a), "r"((uint32_t)(tx)) : "memory")
#define MBAR_WAIT(addr, parity) do {                                              \
    uint32_t _m = (addr); uint32_t _p = (parity); uint32_t _d;                    \
    asm volatile("{ .reg .pred p;\n\t"                                            \
        "mbarrier.try_wait.parity.acquire.cta.shared::cta.b64 p, [%1], %2;\n\t"   \
        "selp.b32 %0, 1, 0, p; }" : "=r"(_d) : "r"(_m), "r"(_p) : "memory");      \
    if (!_d) {                                                                    \
        asm volatile("{ .reg .pred P1;\n\t"                                       \
            "WL_%=:\n\t"                                                          \
            "mbarrier.try_wait.parity.acquire.cta.shared::cta.b64 P1, [%0], %1, 0x989680;\n\t" \
            "@P1 bra.uni WD_%=;\n\t"                                              \
            "bra.uni WL_%=;\n\t"                                                  \
            "WD_%=: }" :: "r"(_m), "r"(_p) : "memory");                           \
    }                                                                             \
} while (0)

// -------- kernel 1: fused normalize (bf16, padded images) + exact diag + zero g_ps --------
__global__ void k_norm_diag(const float* __restrict__ A,
                            const float* __restrict__ P,
                            const float* __restrict__ N) {
    if (blockIdx.x < 512) {
        g_ps[blockIdx.x * 256 + threadIdx.x] = 0.0f;
    }
    int gw   = (blockIdx.x * blockDim.x + threadIdx.x) >> 5;
    int lane = threadIdx.x & 31;
    if (gw >= 2 * BATCH) return;

    if (gw < BATCH) {
        const float* a = A + (size_t)gw * DIM;
        const float* p = P + (size_t)gw * DIM;
        float4 a0 = ((const float4*)a)[lane], a1 = ((const float4*)a)[lane + 32];
        float4 p0 = ((const float4*)p)[lane], p1 = ((const float4*)p)[lane + 32];
        float saa = a0.x*a0.x + a0.y*a0.y + a0.z*a0.z + a0.w*a0.w
                  + a1.x*a1.x + a1.y*a1.y + a1.z*a1.z + a1.w*a1.w;
        float spp = p0.x*p0.x + p0.y*p0.y + p0.z*p0.z + p0.w*p0.w
                  + p1.x*p1.x + p1.y*p1.y + p1.z*p1.z + p1.w*p1.w;
        float sap = a0.x*p0.x + a0.y*p0.y + a0.z*p0.z + a0.w*p0.w
                  + a1.x*p1.x + a1.y*p1.y + a1.z*p1.z + a1.w*p1.w;
        #pragma unroll
        for (int o = 16; o; o >>= 1) {
            saa += __shfl_xor_sync(0xffffffffu, saa, o);
            spp += __shfl_xor_sync(0xffffffffu, spp, o);
            sap += __shfl_xor_sync(0xffffffffu, sap, o);
        }
        float na = fmaxf(sqrtf(saa), 1e-12f);
        float np = fmaxf(sqrtf(spp), 1e-12f);
        float ia = SCALE_A / na;
        float ip = 1.0f / np;
        {
            int R = gw >> 8, r = gw & 255;
            uint8_t* base = g_an + (size_t)R * A_BLOCK + (size_t)r * A_STRIDE;
            *(uint2*)(base + 8 * lane)       = bf16x4(a0, ia);
            *(uint2*)(base + 256 + 8 * lane) = bf16x4(a1, ia);
        }
        {
            int T = gw >> 7, h = (gw >> 6) & 1, r2 = gw & 63;
            uint8_t* b = g_tn + (size_t)(T * 2 + h) * B_BLOCK + (size_t)r2 * B_STRIDE;
            *(uint2*)(b + 8 * lane)       = bf16x4(p0, ip);
            *(uint2*)(b + 256 + 8 * lane) = bf16x4(p1, ip);
        }
        if (lane == 0) g_diag[gw] = sap / (na * np) * SCALE_A;
    } else {
        int j = gw - BATCH;
        const float* n = N + (size_t)j * DIM;
        float4 n0 = ((const float4*)n)[lane], n1 = ((const float4*)n)[lane + 32];
        float s = n0.x*n0.x + n0.y*n0.y + n0.z*n0.z + n0.w*n0.w
                + n1.x*n1.x + n1.y*n1.y + n1.z*n1.z + n1.w*n1.w;
        #pragma unroll
        for (int o = 16; o; o >>= 1) s += __shfl_xor_sync(0xffffffffu, s, o);
        float inv = 1.0f / fmaxf(sqrtf(s), 1e-12f);
        int c = BATCH + j;
        int T = c >> 7, h = (c >> 6) & 1, r2 = c & 63;
        uint8_t* b = g_tn + (size_t)(T * 2 + h) * B_BLOCK + (size_t)r2 * B_STRIDE;
        *(uint2*)(b + 8 * lane)       = bf16x4(n0, inv);
        *(uint2*)(b + 256 + 8 * lane) = bf16x4(n1, inv);
    }
}

// ---------------- SMEM layout ----------------
#define SM_A   0
#define SM_B0  A_BLOCK
#define SM_B1  (SM_B0 + B_BLOCK)
#define MB_A   (SM_B1 + B_BLOCK)
#define MB_F0  (MB_A + 8)
#define MB_F1  (MB_A + 16)
#define MB_C0  (MB_A + 24)
#define MB_C1  (MB_A + 32)
#define SMEM_TOTAL (MB_A + 64)

// ---------------- kernel 2: persistent bf16 mma GEMM + sum-exp2 + fused reduction ----------------
// 256 threads = 8 warps as 4(M) x 2(N); per col-half warp tile 64x32; CTA tile 256x128.
__global__ void __launch_bounds__(256, 1) k_gemm_lse(float* __restrict__ out) {
    extern __shared__ __align__(128) char smem[];
    const uint32_t sb  = smem_u32(smem);
    const uint32_t smA = sb + SM_A;

    const int tid  = threadIdx.x;
    const int lane = tid & 31;
    const int wid  = tid >> 5;
    const int wm   = wid & 3;     // 4 M-warps (64 rows)
    const int wn   = wid >> 2;    // 2 N-warps (32 cols within each 64-col half)

    const int id0 = blockIdx.x * WPC;
    const int id1 = (id0 + WPC < NWORK) ? id0 + WPC : NWORK;

    const int a_row_in    = lane & 15;
    const int a_chunk_add = lane >> 4;
    const int b_row_in    = (lane & 7) + ((lane >> 4) << 3);
    const int b_chunk_add = (lane >> 3) & 1;

    if (tid == 0) {
        MBAR_INIT(sb + MB_A, 1);
        MBAR_INIT(sb + MB_F0, 1);
        MBAR_INIT(sb + MB_F1, 1);
        MBAR_INIT(sb + MB_C0, 256);
        MBAR_INIT(sb + MB_C1, 256);
    }
    __syncthreads();

    int rb = id0 >> 7;
    if (tid < 4) {
        if (tid == 0) MBAR_ARRIVE_TX(sb + MB_A, A_BLOCK);
        const uint8_t* srcA = g_an + (size_t)rb * A_BLOCK + tid * (A_BLOCK / 4);
        bulk_g2s(smA + tid * (A_BLOCK / 4), srcA, A_BLOCK / 4, sb + MB_A);
    }
    {
        int ct0 = id0 & 127;
        if (tid == 0) {
            MBAR_ARRIVE_TX(sb + MB_F0, B_BLOCK);
            bulk_g2s(sb + SM_B0, g_tn + (size_t)(ct0 * 2 + 0) * B_BLOCK, B_BLOCK, sb + MB_F0);
        }
        if (tid == 32) {
            MBAR_ARRIVE_TX(sb + MB_F1, B_BLOCK);
            bulk_g2s(sb + SM_B1, g_tn + (size_t)(ct0 * 2 + 1) * B_BLOCK, B_BLOCK, sb + MB_F1);
        }
    }
    int aph = 0;
    MBAR_WAIT(sb + MB_A, aph); aph ^= 1;

    float rs[4][2];
    #pragma unroll
    for (int i = 0; i < 4; ++i) { rs[i][0] = 0.f; rs[i][1] = 0.f; }

    int f0 = 0, f1 = 0, c0 = 0, c1 = 0;
    const int slot_base = (blockIdx.x & 7) * 2 + wn;   // 0..15

    for (int id = id0; id < id1; ++id) {
        const int nrb = id >> 7;
        if (nrb != rb) {
            #pragma unroll
            for (int i = 0; i < 4; ++i)
                #pragma unroll
                for (int hh = 0; hh < 2; ++hh) {
                    rs[i][hh] += __shfl_xor_sync(0xffffffffu, rs[i][hh], 1);
                    rs[i][hh] += __shfl_xor_sync(0xffffffffu, rs[i][hh], 2);
                }
            if ((lane & 3) == 0) {
                #pragma unroll
                for (int i = 0; i < 4; ++i) {
                    int r = rb * ROWS_CTA + wm * 64 + i * 16 + (lane >> 2);
                    g_ps[slot_base * BATCH + r]     = rs[i][0];
                    g_ps[slot_base * BATCH + r + 8] = rs[i][1];
                }
            }
            #pragma unroll
            for (int i = 0; i < 4; ++i) { rs[i][0] = 0.f; rs[i][1] = 0.f; }

            __syncthreads();
            rb = nrb;
            if (tid < 4) {
                if (tid == 0) MBAR_ARRIVE_TX(sb + MB_A, A_BLOCK);
                const uint8_t* srcA = g_an + (size_t)rb * A_BLOCK + tid * (A_BLOCK / 4);
                bulk_g2s(smA + tid * (A_BLOCK / 4), srcA, A_BLOCK / 4, sb + MB_A);
            }
            MBAR_WAIT(sb + MB_A, aph); aph ^= 1;
        }

        // two independent col-half chunks per tile; epilogue of chunk h overlaps
        // MMA of chunk h+1 (no shared accumulator, no convergence barrier between)
        #pragma unroll
        for (int h = 0; h < 2; ++h) {
            const uint32_t smB = sb + (h ? SM_B1 : SM_B0);
            if (h) { MBAR_WAIT(sb + MB_F1, f1); f1 ^= 1; }
            else   { MBAR_WAIT(sb + MB_F0, f0); f0 ^= 1; }

            float acc[4][4][4];
            #pragma unroll
            for (int i = 0; i < 4; ++i)
                #pragma unroll
                for (int j = 0; j < 4; ++j)
                    #pragma unroll
                    for (int c = 0; c < 4; ++c) acc[i][j][c] = 0.0f;

            #pragma unroll
            for (int step = 0; step < 16; ++step) {
                uint32_t af[4][4];
                #pragma unroll
                for (int i = 0; i < 4; ++i) {
                    int row = wm * 64 + i * 16 + a_row_in;
                    int chunk = step * 2 + a_chunk_add;
                    ldsm_x4(af[i], smA + row * A_STRIDE + (chunk << 4));
                }
                uint32_t bf[2][4];
                #pragma unroll
                for (int p = 0; p < 2; ++p) {
                    int row = wn * 32 + p * 16 + b_row_in;
                    int chunk = step * 2 + b_chunk_add;
                    ldsm_x4(bf[p], smB + row * B_STRIDE + (chunk << 4));
                }
                #pragma unroll
                for (int i = 0; i < 4; ++i)
                    #pragma unroll
                    for (int j = 0; j < 4; ++j)
                        mma16816(acc[i][j], af[i], &bf[j >> 1][(j & 1) * 2]);
            }

            if (h == 0) {
                MBAR_ARRIVE(sb + MB_C0);
                if (tid == 0 && id + 1 < id1) {
                    MBAR_WAIT(sb + MB_C0, c0); c0 ^= 1;
                    int nct = (id + 1) & 127;
                    MBAR_ARRIVE_TX(sb + MB_F0, B_BLOCK);
                    bulk_g2s(sb + SM_B0, g_tn + (size_t)(nct * 2 + 0) * B_BLOCK,
                             B_BLOCK, sb + MB_F0);
                }
            } else {
                MBAR_ARRIVE(sb + MB_C1);
                if (tid == 32 && id + 1 < id1) {
                    MBAR_WAIT(sb + MB_C1, c1); c1 ^= 1;
                    int nct = (id + 1) & 127;
                    MBAR_ARRIVE_TX(sb + MB_F1, B_BLOCK);
                    bulk_g2s(sb + SM_B1, g_tn + (size_t)(nct * 2 + 1) * B_BLOCK,
                             B_BLOCK, sb + MB_F1);
                }
            }

            // chunk epilogue: independent of the other chunk's MMA -> overlaps it
            #pragma unroll
            for (int i = 0; i < 4; ++i) {
                float s0 = 0.f, s1 = 0.f;
                #pragma unroll
                for (int j = 0; j < 4; ++j) {
                    s0 += ex2f(acc[i][j][0]) + ex2f(acc[i][j][1]);
                    s1 += ex2f(acc[i][j][2]) + ex2f(acc[i][j][3]);
                }
                rs[i][0] += s0;
                rs[i][1] += s1;
            }
        }
    }

    #pragma unroll
    for (int i = 0; i < 4; ++i)
        #pragma unroll
        for (int hh = 0; hh < 2; ++hh) {
            rs[i][hh] += __shfl_xor_sync(0xffffffffu, rs[i][hh], 1);
            rs[i][hh] += __shfl_xor_sync(0xffffffffu, rs[i][hh], 2);
        }
    if ((lane & 3) == 0) {
        #pragma unroll
        for (int i = 0; i < 4; ++i) {
            int r = rb * ROWS_CTA + wm * 64 + i * 16 + (lane >> 2);
            g_ps[slot_base * BATCH + r]     = rs[i][0];
            g_ps[slot_base * BATCH + r + 8] = rs[i][1];
        }
    }

    // ---- fused final reduction (device-wide sync; all CTAs are one wave) ----
    __threadfence();
    __syncthreads();
    if (tid == 0) atomicAdd(&g_done, 1u);

    if (blockIdx.x < 32) {
        if (tid == 0) {
            while (atomicAdd(&g_done, 0u) < (unsigned)GRID_G) { }
        }
        __syncthreads();

        const int row = blockIdx.x * 256 + tid;
        float s = 0.0f;
        #pragma unroll
        for (int j = 0; j < 16; ++j) s += g_ps[j * BATCH + row];
        float v = log2f(s) - g_diag[row];

        __shared__ double sd[256];
        sd[tid] = (double)v;
        __syncthreads();
        #pragma unroll
        for (int k = 128; k > 0; k >>= 1) {
            if (tid < k) sd[tid] += sd[tid + k];
            __syncthreads();
        }
        if (tid == 0) {
            atomicAdd(&g_loss, sd[0]);
            __threadfence();
            unsigned t = atomicAdd(&g_tick, 1u);
            if (t == 31u) {
                double total = atomicAdd(&g_loss, 0.0);
                out[0] = (float)(total * LN2_D / (double)BATCH);
                g_loss = 0.0;
                g_tick = 0u;
                g_done = 0u;
                __threadfence();
            }
        }
    }
}

// ---------------- launcher ----------------
extern "C" void kernel_launch(void* const* d_in, const int* in_sizes, int n_in,
                              void* d_out, int out_size) {
    const float* A = (const float*)d_in[0];
    const float* P = (const float*)d_in[1];
    const float* N = (const float*)d_in[2];
    float* out = (float*)d_out;

    cudaFuncSetAttribute(k_gemm_lse, cudaFuncAttributeMaxDynamicSharedMemorySize,
                         SMEM_TOTAL);

    k_norm_diag<<<(2 * BATCH) / 8, 256>>>(A, P, N);
    k_gemm_lse<<<GRID_G, 256, SMEM_TOTAL>>>(out);
}

// round 14
// speedup vs baseline: 1.2785x; 1.2785x over previous
#include <cuda_runtime.h>
#include <cuda_bf16.h>
#include <cstdint>

// ---------------- problem constants ----------------
#define BATCH 8192
#define DIM   256
#define TGT   16384
#define ROWS_CTA 256
#define NRB   (BATCH / ROWS_CTA)          // 32 row-blocks
#define NCT   (TGT / 128)                 // 128 col-tiles
#define NWORK (NRB * NCT)                 // 4096 work units
#define WPC   28                          // tiles per CTA (contiguous)
#define GRID_G 147                        // one wave (148 resident CTAs max)
#define SCALE_A  28.8539008177792681f     // (1/0.05) * log2(e)
#define LN2_D    0.69314718055994530942

// Padded operand-image strides
#define A_STRIDE 528                       // 512 B data + 16 skew
#define B_STRIDE 528
#define A_BLOCK  (ROWS_CTA * A_STRIDE)     // 135168
#define Q_BLOCK  (32 * B_STRIDE)           // 16896 per (tile, col-quarter)

// ---------------- scratch (device globals; pre-padded images) ----------------
__device__ __align__(1024) uint8_t g_an[NRB * A_BLOCK];
__device__ __align__(1024) uint8_t g_tn[NCT * 4 * Q_BLOCK];
__device__ float  g_diag[BATCH];
__device__ float  g_ps[16 * BATCH];
__device__ double g_loss = 0.0;
__device__ unsigned g_tick = 0;
__device__ unsigned g_done = 0;

// ---------------- helpers ----------------
__device__ __forceinline__ uint32_t smem_u32(const void* p) {
    uint32_t a;
    asm("{ .reg .u64 t; cvta.to.shared.u64 t, %1; cvt.u32.u64 %0, t; }" : "=r"(a) : "l"(p));
    return a;
}
__device__ __forceinline__ float ex2f(float x) {
    float y; asm("ex2.approx.f32 %0, %1;" : "=f"(y) : "f"(x)); return y;
}
__device__ __forceinline__ uint2 bf16x4(float4 v, float s) {
    uint2 r;
    __nv_bfloat162 lo = __floats2bfloat162_rn(v.x * s, v.y * s);
    __nv_bfloat162 hi = __floats2bfloat162_rn(v.z * s, v.w * s);
    r.x = *(uint32_t*)&lo; r.y = *(uint32_t*)&hi;
    return r;
}
__device__ __forceinline__ void ldsm_x4(uint32_t* r, uint32_t addr) {
    asm volatile("ldmatrix.sync.aligned.m8n8.x4.shared.b16 {%0,%1,%2,%3}, [%4];"
        : "=r"(r[0]), "=r"(r[1]), "=r"(r[2]), "=r"(r[3]) : "r"(addr));
}
__device__ __forceinline__ void mma16816(float* d, const uint32_t* a, const uint32_t* b) {
    asm volatile("mma.sync.aligned.m16n8k16.row.col.f32.bf16.bf16.f32 "
        "{%0,%1,%2,%3}, {%4,%5,%6,%7}, {%8,%9}, {%0,%1,%2,%3};"
        : "+f"(d[0]), "+f"(d[1]), "+f"(d[2]), "+f"(d[3])
        : "r"(a[0]), "r"(a[1]), "r"(a[2]), "r"(a[3]), "r"(b[0]), "r"(b[1]));
}
__device__ __forceinline__ void bulk_g2s(uint32_t dst, const void* src,
                                         uint32_t bytes, uint32_t mbar) {
    asm volatile("cp.async.bulk.shared::cluster.global.mbarrier::complete_tx::bytes "
                 "[%0], [%1], %2, [%3];"
                 :: "r"(dst), "l"(src), "r"(bytes), "r"(mbar) : "memory");
}
#define MBAR_INIT(a, c) asm volatile("mbarrier.init.shared.b64 [%0], %1;" :: "r"(a), "r"((uint32_t)(c)) : "memory")
#define MBAR_ARRIVE(a)  asm volatile("mbarrier.arrive.shared.b64 _, [%0];" :: "r"(a) : "memory")
#define MBAR_ARRIVE_TX(a, tx) asm volatile("mbarrier.arrive.expect_tx.shared.b64 _, [%0], %1;" :: "r"(a), "r"((uint32_t)(tx)) : "memory")
#define MBAR_WAIT(addr, parity) do {                                              \
    uint32_t _m = (addr); uint32_t _p = (parity); uint32_t _d;                    \
    asm volatile("{ .reg .pred p;\n\t"                                            \
        "mbarrier.try_wait.parity.acquire.cta.shared::cta.b64 p, [%1], %2;\n\t"   \
        "selp.b32 %0, 1, 0, p; }" : "=r"(_d) : "r"(_m), "r"(_p) : "memory");      \
    if (!_d) {                                                                    \
        asm volatile("{ .reg .pred P1;\n\t"                                       \
            "WL_%=:\n\t"                                                          \
            "mbarrier.try_wait.parity.acquire.cta.shared::cta.b64 P1, [%0], %1, 0x989680;\n\t" \
            "@P1 bra.uni WD_%=;\n\t"                                              \
            "bra.uni WL_%=;\n\t"                                                  \
            "WD_%=: }" :: "r"(_m), "r"(_p) : "memory");                           \
    }                                                                             \
} while (0)

// -------- kernel 1: fused normalize (bf16, padded images) + exact diag + zero g_ps --------
__global__ void k_norm_diag(const float* __restrict__ A,
                            const float* __restrict__ P,
                            const float* __restrict__ N) {
    if (blockIdx.x < 512) {
        g_ps[blockIdx.x * 256 + threadIdx.x] = 0.0f;
    }
    int gw   = (blockIdx.x * blockDim.x + threadIdx.x) >> 5;
    int lane = threadIdx.x & 31;
    if (gw >= 2 * BATCH) return;

    if (gw < BATCH) {
        const float* a = A + (size_t)gw * DIM;
        const float* p = P + (size_t)gw * DIM;
        float4 a0 = ((const float4*)a)[lane], a1 = ((const float4*)a)[lane + 32];
        float4 p0 = ((const float4*)p)[lane], p1 = ((const float4*)p)[lane + 32];
        float saa = a0.x*a0.x + a0.y*a0.y + a0.z*a0.z + a0.w*a0.w
                  + a1.x*a1.x + a1.y*a1.y + a1.z*a1.z + a1.w*a1.w;
        float spp = p0.x*p0.x + p0.y*p0.y + p0.z*p0.z + p0.w*p0.w
                  + p1.x*p1.x + p1.y*p1.y + p1.z*p1.z + p1.w*p1.w;
        float sap = a0.x*p0.x + a0.y*p0.y + a0.z*p0.z + a0.w*p0.w
                  + a1.x*p1.x + a1.y*p1.y + a1.z*p1.z + a1.w*p1.w;
        #pragma unroll
        for (int o = 16; o; o >>= 1) {
            saa += __shfl_xor_sync(0xffffffffu, saa, o);
            spp += __shfl_xor_sync(0xffffffffu, spp, o);
            sap += __shfl_xor_sync(0xffffffffu, sap, o);
        }
        float na = fmaxf(sqrtf(saa), 1e-12f);
        float np = fmaxf(sqrtf(spp), 1e-12f);
        float ia = SCALE_A / na;
        float ip = 1.0f / np;
        {
            int R = gw >> 8, r = gw & 255;
            uint8_t* base = g_an + (size_t)R * A_BLOCK + (size_t)r * A_STRIDE;
            *(uint2*)(base + 8 * lane)       = bf16x4(a0, ia);
            *(uint2*)(base + 256 + 8 * lane) = bf16x4(a1, ia);
        }
        {
            int T = gw >> 7, q = (gw >> 5) & 3, r2 = gw & 31;
            uint8_t* b = g_tn + (size_t)(T * 4 + q) * Q_BLOCK + (size_t)r2 * B_STRIDE;
            *(uint2*)(b + 8 * lane)       = bf16x4(p0, ip);
            *(uint2*)(b + 256 + 8 * lane) = bf16x4(p1, ip);
        }
        if (lane == 0) g_diag[gw] = sap / (na * np) * SCALE_A;
    } else {
        int j = gw - BATCH;
        const float* n = N + (size_t)j * DIM;
        float4 n0 = ((const float4*)n)[lane], n1 = ((const float4*)n)[lane + 32];
        float s = n0.x*n0.x + n0.y*n0.y + n0.z*n0.z + n0.w*n0.w
                + n1.x*n1.x + n1.y*n1.y + n1.z*n1.z + n1.w*n1.w;
        #pragma unroll
        for (int o = 16; o; o >>= 1) s += __shfl_xor_sync(0xffffffffu, s, o);
        float inv = 1.0f / fmaxf(sqrtf(s), 1e-12f);
        int c = BATCH + j;
        int T = c >> 7, q = (c >> 5) & 3, r2 = c & 31;
        uint8_t* b = g_tn + (size_t)(T * 4 + q) * Q_BLOCK + (size_t)r2 * B_STRIDE;
        *(uint2*)(b + 8 * lane)       = bf16x4(n0, inv);
        *(uint2*)(b + 256 + 8 * lane) = bf16x4(n1, inv);
    }
}

// ---------------- SMEM layout ----------------
#define SM_A    0
#define SM_B(q) (A_BLOCK + (q) * Q_BLOCK)          // 4 quarter buffers
#define MB_A    (A_BLOCK + 4 * Q_BLOCK)            // 202752
#define MB_F(q) (MB_A + 8  + (q) * 8)
#define MB_C(q) (MB_A + 40 + (q) * 8)
#define SMEM_TOTAL (MB_A + 72)

// ---------------- kernel 2: persistent bf16 mma GEMM, 4-quarter B ring + fused reduction ----------------
// 256 threads = 8 warps as 4(M) x 2(N); per quarter warp tile 64x16; CTA tile 256x128.
__global__ void __launch_bounds__(256, 1) k_gemm_lse(float* __restrict__ out) {
    extern __shared__ __align__(128) char smem[];
    const uint32_t sb  = smem_u32(smem);
    const uint32_t smA = sb + SM_A;

    const int tid  = threadIdx.x;
    const int lane = tid & 31;
    const int wid  = tid >> 5;
    const int wm   = wid & 3;     // 4 M-warps (64 rows)
    const int wn   = wid >> 2;    // 2 N-warps (16 cols per 32-col quarter)

    const int id0 = blockIdx.x * WPC;
    const int id1 = (id0 + WPC < NWORK) ? id0 + WPC : NWORK;

    const int a_row_in    = lane & 15;
    const int a_chunk_add = lane >> 4;
    const int b_row_in    = (lane & 7) + ((lane >> 4) << 3);
    const int b_chunk_add = (lane >> 3) & 1;

    if (tid == 0) {
        MBAR_INIT(sb + MB_A, 1);
        #pragma unroll
        for (int q = 0; q < 4; ++q) {
            MBAR_INIT(sb + MB_F(q), 1);
            MBAR_INIT(sb + MB_C(q), 256);
        }
    }
    __syncthreads();

    int rb = id0 >> 7;
    if (tid < 4) {
        if (tid == 0) MBAR_ARRIVE_TX(sb + MB_A, A_BLOCK);
        const uint8_t* srcA = g_an + (size_t)rb * A_BLOCK + tid * (A_BLOCK / 4);
        bulk_g2s(smA + tid * (A_BLOCK / 4), srcA, A_BLOCK / 4, sb + MB_A);
    }
    if (tid < 128 && (tid & 31) == 0) {
        int q   = tid >> 5;
        int ct0 = id0 & 127;
        MBAR_ARRIVE_TX(sb + MB_F(q), Q_BLOCK);
        bulk_g2s(sb + SM_B(q), g_tn + (size_t)(ct0 * 4 + q) * Q_BLOCK, Q_BLOCK, sb + MB_F(q));
    }
    int aph = 0;
    MBAR_WAIT(sb + MB_A, aph); aph ^= 1;

    float rs[4][2];
    #pragma unroll
    for (int i = 0; i < 4; ++i) { rs[i][0] = 0.f; rs[i][1] = 0.f; }

    const int slot_base = (blockIdx.x & 7) * 2 + wn;   // 0..15
    const int myq = wid;                                // warps 0-3 own quarter refills

    // precompute A/B addressing
    uint32_t a_base[4];
    #pragma unroll
    for (int i = 0; i < 4; ++i)
        a_base[i] = smA + (wm * 64 + i * 16 + a_row_in) * A_STRIDE;
    const uint32_t b_off = (wn * 16 + b_row_in) * B_STRIDE;

    for (int id = id0; id < id1; ++id) {
        const int tp = (id - id0) & 1;     // tile parity -> barrier phases
        const int nrb = id >> 7;
        if (nrb != rb) {
            #pragma unroll
            for (int i = 0; i < 4; ++i)
                #pragma unroll
                for (int hh = 0; hh < 2; ++hh) {
                    rs[i][hh] += __shfl_xor_sync(0xffffffffu, rs[i][hh], 1);
                    rs[i][hh] += __shfl_xor_sync(0xffffffffu, rs[i][hh], 2);
                }
            if ((lane & 3) == 0) {
                #pragma unroll
                for (int i = 0; i < 4; ++i) {
                    int r = rb * ROWS_CTA + wm * 64 + i * 16 + (lane >> 2);
                    g_ps[slot_base * BATCH + r]     = rs[i][0];
                    g_ps[slot_base * BATCH + r + 8] = rs[i][1];
                }
            }
            #pragma unroll
            for (int i = 0; i < 4; ++i) { rs[i][0] = 0.f; rs[i][1] = 0.f; }

            __syncthreads();
            rb = nrb;
            if (tid < 4) {
                if (tid == 0) MBAR_ARRIVE_TX(sb + MB_A, A_BLOCK);
                const uint8_t* srcA = g_an + (size_t)rb * A_BLOCK + tid * (A_BLOCK / 4);
                bulk_g2s(smA + tid * (A_BLOCK / 4), srcA, A_BLOCK / 4, sb + MB_A);
            }
            MBAR_WAIT(sb + MB_A, aph); aph ^= 1;
        }

        // four independent 32-col quarters per tile; epilogue of quarter q
        // overlaps MMA of quarter q+1; refills have 3 quarters of slack
        #pragma unroll
        for (int q = 0; q < 4; ++q) {
            const uint32_t smB = sb + SM_B(q);
            MBAR_WAIT(sb + MB_F(q), tp);

            float acc[4][2][4];
            #pragma unroll
            for (int i = 0; i < 4; ++i)
                #pragma unroll
                for (int j = 0; j < 2; ++j)
                    #pragma unroll
                    for (int c = 0; c < 4; ++c) acc[i][j][c] = 0.0f;

            #pragma unroll
            for (int step = 0; step < 16; ++step) {
                uint32_t af[4][4];
                const int ca = step * 2 + a_chunk_add;
                #pragma unroll
                for (int i = 0; i < 4; ++i)
                    ldsm_x4(af[i], a_base[i] + (ca << 4));
                uint32_t bf[4];
                const int cb = step * 2 + b_chunk_add;
                ldsm_x4(bf, smB + b_off + (cb << 4));
                #pragma unroll
                for (int i = 0; i < 4; ++i)
                    #pragma unroll
                    for (int j = 0; j < 2; ++j)
                        mma16816(acc[i][j], af[i], &bf[j * 2]);
            }

            MBAR_ARRIVE(sb + MB_C(q));
            if (wid == q && lane == 0 && id + 1 < id1) {
                MBAR_WAIT(sb + MB_C(q), tp);
                const int nct = (id + 1) & 127;
                MBAR_ARRIVE_TX(sb + MB_F(q), Q_BLOCK);
                bulk_g2s(sb + SM_B(q), g_tn + (size_t)(nct * 4 + q) * Q_BLOCK,
                         Q_BLOCK, sb + MB_F(q));
            }

            // quarter epilogue: independent accs -> overlaps next quarter's MMA
            #pragma unroll
            for (int i = 0; i < 4; ++i) {
                float s0 = 0.f, s1 = 0.f;
                #pragma unroll
                for (int j = 0; j < 2; ++j) {
                    s0 += ex2f(acc[i][j][0]) + ex2f(acc[i][j][1]);
                    s1 += ex2f(acc[i][j][2]) + ex2f(acc[i][j][3]);
                }
                rs[i][0] += s0;
                rs[i][1] += s1;
            }
        }
    }

    #pragma unroll
    for (int i = 0; i < 4; ++i)
        #pragma unroll
        for (int hh = 0; hh < 2; ++hh) {
            rs[i][hh] += __shfl_xor_sync(0xffffffffu, rs[i][hh], 1);
            rs[i][hh] += __shfl_xor_sync(0xffffffffu, rs[i][hh], 2);
        }
    if ((lane & 3) == 0) {
        #pragma unroll
        for (int i = 0; i < 4; ++i) {
            int r = rb * ROWS_CTA + wm * 64 + i * 16 + (lane >> 2);
            g_ps[slot_base * BATCH + r]     = rs[i][0];
            g_ps[slot_base * BATCH + r + 8] = rs[i][1];
        }
    }

    // ---- fused final reduction (device-wide sync; all 147 CTAs are one wave) ----
    __threadfence();
    __syncthreads();
    if (tid == 0) atomicAdd(&g_done, 1u);

    if (blockIdx.x < 32) {
        if (tid == 0) {
            while (atomicAdd(&g_done, 0u) < (unsigned)GRID_G) { }
        }
        __syncthreads();

        const int row = blockIdx.x * 256 + tid;
        float s = 0.0f;
        #pragma unroll
        for (int j = 0; j < 16; ++j) s += g_ps[j * BATCH + row];
        float v = log2f(s) - g_diag[row];

        __shared__ double sd[256];
        sd[tid] = (double)v;
        __syncthreads();
        #pragma unroll
        for (int k = 128; k > 0; k >>= 1) {
            if (tid < k) sd[tid] += sd[tid + k];
            __syncthreads();
        }
        if (tid == 0) {
            atomicAdd(&g_loss, sd[0]);
            __threadfence();
            unsigned t = atomicAdd(&g_tick, 1u);
            if (t == 31u) {
                double total = atomicAdd(&g_loss, 0.0);
                out[0] = (float)(total * LN2_D / (double)BATCH);
                g_loss = 0.0;
                g_tick = 0u;
                g_done = 0u;
                __threadfence();
            }
        }
    }
}

// ---------------- launcher ----------------
extern "C" void kernel_launch(void* const* d_in, const int* in_sizes, int n_in,
                              void* d_out, int out_size) {
    const float* A = (const float*)d_in[0];
    const float* P = (const float*)d_in[1];
    const float* N = (const float*)d_in[2];
    float* out = (float*)d_out;

    cudaFuncSetAttribute(k_gemm_lse, cudaFuncAttributeMaxDynamicSharedMemorySize,
                         SMEM_TOTAL);

    k_norm_diag<<<(2 * BATCH) / 8, 256>>>(A, P, N);
    k_gemm_lse<<<GRID_G, 256, SMEM_TOTAL>>>(out);
}

// round 15
// speedup vs baseline: 1.4627x; 1.1441x over previous
#include <cuda_runtime.h>
#include <cuda_bf16.h>
#include <cstdint>

// ---------------- problem constants ----------------
#define BATCH 8192
#define DIM   256
#define TGT   16384
#define ROWS_CTA 256
#define NRB   (BATCH / ROWS_CTA)          // 32 row-blocks
#define NCT   (TGT / 128)                 // 128 col-tiles
#define NWORK (NRB * NCT)                 // 4096 work units
#define WPC   28                          // tiles per CTA (contiguous)
#define GRID_G 147                        // one wave (148 resident CTAs max)
#define SCALE_A  28.8539008177792681f     // (1/0.05) * log2(e)
#define LN2_D    0.69314718055994530942

// Padded operand-image strides
#define A_STRIDE 528                       // 512 B data + 16 skew
#define B_STRIDE 528                       // 512 B data + 16 skew (full K per row)
#define A_BLOCK  (ROWS_CTA * A_STRIDE)     // 135168
#define B_BLOCK  (64 * B_STRIDE)           // 33792 per (tile, col-half)

// ---------------- scratch (device globals; pre-padded images) ----------------
__device__ __align__(1024) uint8_t g_an[NRB * A_BLOCK];
__device__ __align__(1024) uint8_t g_tn[NCT * 2 * B_BLOCK];
__device__ float  g_diag[BATCH];
__device__ float  g_ps[16 * BATCH];
__device__ double g_loss = 0.0;
__device__ unsigned g_tick = 0;
__device__ unsigned g_done = 0;

// ---------------- helpers ----------------
__device__ __forceinline__ uint32_t smem_u32(const void* p) {
    uint32_t a;
    asm("{ .reg .u64 t; cvta.to.shared.u64 t, %1; cvt.u32.u64 %0, t; }" : "=r"(a) : "l"(p));
    return a;
}
__device__ __forceinline__ float ex2f(float x) {
    float y; asm("ex2.approx.f32 %0, %1;" : "=f"(y) : "f"(x)); return y;
}
__device__ __forceinline__ uint2 bf16x4(float4 v, float s) {
    uint2 r;
    __nv_bfloat162 lo = __floats2bfloat162_rn(v.x * s, v.y * s);
    __nv_bfloat162 hi = __floats2bfloat162_rn(v.z * s, v.w * s);
    r.x = *(uint32_t*)&lo; r.y = *(uint32_t*)&hi;
    return r;
}
__device__ __forceinline__ void ldsm_x4(uint32_t* r, uint32_t addr) {
    asm volatile("ldmatrix.sync.aligned.m8n8.x4.shared.b16 {%0,%1,%2,%3}, [%4];"
        : "=r"(r[0]), "=r"(r[1]), "=r"(r[2]), "=r"(r[3]) : "r"(addr));
}
__device__ __forceinline__ void mma16816(float* d, const uint32_t* a, const uint32_t* b) {
    asm volatile("mma.sync.aligned.m16n8k16.row.col.f32.bf16.bf16.f32 "
        "{%0,%1,%2,%3}, {%4,%5,%6,%7}, {%8,%9}, {%0,%1,%2,%3};"
        : "+f"(d[0]), "+f"(d[1]), "+f"(d[2]), "+f"(d[3])
        : "r"(a[0]), "r"(a[1]), "r"(a[2]), "r"(a[3]), "r"(b[0]), "r"(b[1]));
}
__device__ __forceinline__ void bulk_g2s(uint32_t dst, const void* src,
                                         uint32_t bytes, uint32_t mbar) {
    asm volatile("cp.async.bulk.shared::cluster.global.mbarrier::complete_tx::bytes "
                 "[%0], [%1], %2, [%3];"
                 :: "r"(dst), "l"(src), "r"(bytes), "r"(mbar) : "memory");
}
#define MBAR_INIT(a, c) asm volatile("mbarrier.init.shared.b64 [%0], %1;" :: "r"(a), "r"((uint32_t)(c)) : "memory")
#define MBAR_ARRIVE(a)  asm volatile("mbarrier.arrive.shared.b64 _, [%0];" :: "r"(a) : "memory")
#define MBAR_ARRIVE_TX(a, tx) asm volatile("mbarrier.arrive.expect_tx.shared.b64 _, [%0], %1;" :: "r"(a), "r"((uint32_t)(tx)) : "memory")
#define MBAR_WAIT(addr, parity) do {                                              \
    uint32_t _m = (addr); uint32_t _p = (parity); uint32_t _d;                    \
    asm volatile("{ .reg .pred p;\n\t"                                            \
        "mbarrier.try_wait.parity.acquire.cta.shared::cta.b64 p, [%1], %2;\n\t"   \
        "selp.b32 %0, 1, 0, p; }" : "=r"(_d) : "r"(_m), "r"(_p) : "memory");      \
    if (!_d) {                                                                    \
        asm volatile("{ .reg .pred P1;\n\t"                                       \
            "WL_%=:\n\t"                                                          \
            "mbarrier.try_wait.parity.acquire.cta.shared::cta.b64 P1, [%0], %1, 0x989680;\n\t" \
            "@P1 bra.uni WD_%=;\n\t"                                              \
            "bra.uni WL_%=;\n\t"                                                  \
            "WD_%=: }" :: "r"(_m), "r"(_p) : "memory");                           \
    }                                                                             \
} while (0)

// -------- kernel 1: fused normalize (bf16, padded images) + exact diag + zero g_ps --------
__global__ void k_norm_diag(const float* __restrict__ A,
                            const float* __restrict__ P,
                            const float* __restrict__ N) {
    if (blockIdx.x < 512) {
        g_ps[blockIdx.x * 256 + threadIdx.x] = 0.0f;
    }
    int gw   = (blockIdx.x * blockDim.x + threadIdx.x) >> 5;
    int lane = threadIdx.x & 31;
    if (gw >= 2 * BATCH) return;

    if (gw < BATCH) {
        const float* a = A + (size_t)gw * DIM;
        const float* p = P + (size_t)gw * DIM;
        float4 a0 = ((const float4*)a)[lane], a1 = ((const float4*)a)[lane + 32];
        float4 p0 = ((const float4*)p)[lane], p1 = ((const float4*)p)[lane + 32];
        float saa = a0.x*a0.x + a0.y*a0.y + a0.z*a0.z + a0.w*a0.w
                  + a1.x*a1.x + a1.y*a1.y + a1.z*a1.z + a1.w*a1.w;
        float spp = p0.x*p0.x + p0.y*p0.y + p0.z*p0.z + p0.w*p0.w
                  + p1.x*p1.x + p1.y*p1.y + p1.z*p1.z + p1.w*p1.w;
        float sap = a0.x*p0.x + a0.y*p0.y + a0.z*p0.z + a0.w*p0.w
                  + a1.x*p1.x + a1.y*p1.y + a1.z*p1.z + a1.w*p1.w;
        #pragma unroll
        for (int o = 16; o; o >>= 1) {
            saa += __shfl_xor_sync(0xffffffffu, saa, o);
            spp += __shfl_xor_sync(0xffffffffu, spp, o);
            sap += __shfl_xor_sync(0xffffffffu, sap, o);
        }
        float na = fmaxf(sqrtf(saa), 1e-12f);
        float np = fmaxf(sqrtf(spp), 1e-12f);
        float ia = SCALE_A / na;
        float ip = 1.0f / np;
        {
            int R = gw >> 8, r = gw & 255;
            uint8_t* base = g_an + (size_t)R * A_BLOCK + (size_t)r * A_STRIDE;
            *(uint2*)(base + 8 * lane)       = bf16x4(a0, ia);
            *(uint2*)(base + 256 + 8 * lane) = bf16x4(a1, ia);
        }
        {
            int T = gw >> 7, h = (gw >> 6) & 1, r2 = gw & 63;
            uint8_t* b = g_tn + (size_t)(T * 2 + h) * B_BLOCK + (size_t)r2 * B_STRIDE;
            *(uint2*)(b + 8 * lane)       = bf16x4(p0, ip);
            *(uint2*)(b + 256 + 8 * lane) = bf16x4(p1, ip);
        }
        if (lane == 0) g_diag[gw] = sap / (na * np) * SCALE_A;
    } else {
        int j = gw - BATCH;
        const float* n = N + (size_t)j * DIM;
        float4 n0 = ((const float4*)n)[lane], n1 = ((const float4*)n)[lane + 32];
        float s = n0.x*n0.x + n0.y*n0.y + n0.z*n0.z + n0.w*n0.w
                + n1.x*n1.x + n1.y*n1.y + n1.z*n1.z + n1.w*n1.w;
        #pragma unroll
        for (int o = 16; o; o >>= 1) s += __shfl_xor_sync(0xffffffffu, s, o);
        float inv = 1.0f / fmaxf(sqrtf(s), 1e-12f);
        int c = BATCH + j;
        int T = c >> 7, h = (c >> 6) & 1, r2 = c & 63;
        uint8_t* b = g_tn + (size_t)(T * 2 + h) * B_BLOCK + (size_t)r2 * B_STRIDE;
        *(uint2*)(b + 8 * lane)       = bf16x4(n0, inv);
        *(uint2*)(b + 256 + 8 * lane) = bf16x4(n1, inv);
    }
}

// ---------------- SMEM layout ----------------
#define SM_A   0
#define SM_B0  A_BLOCK
#define SM_B1  (SM_B0 + B_BLOCK)
#define MB_A   (SM_B1 + B_BLOCK)
#define MB_F0  (MB_A + 8)
#define MB_F1  (MB_A + 16)
#define MB_C0  (MB_A + 24)
#define MB_C1  (MB_A + 32)
#define SMEM_TOTAL (MB_A + 64)

// ---------------- kernel 2: persistent bf16 mma GEMM + sum-exp2 + fused reduction ----------------
// 256 threads = 8 warps as 4(M) x 2(N); per col-half warp tile 64x32; CTA tile 256x128.
__global__ void __launch_bounds__(256, 1) k_gemm_lse(float* __restrict__ out) {
    extern __shared__ __align__(128) char smem[];
    const uint32_t sb  = smem_u32(smem);
    const uint32_t smA = sb + SM_A;

    const int tid  = threadIdx.x;
    const int lane = tid & 31;
    const int wid  = tid >> 5;
    const int wm   = wid & 3;     // 4 M-warps (64 rows)
    const int wn   = wid >> 2;    // 2 N-warps (32 cols within each 64-col half)

    const int id0 = blockIdx.x * WPC;
    const int id1 = (id0 + WPC < NWORK) ? id0 + WPC : NWORK;

    const int a_row_in    = lane & 15;
    const int a_chunk_add = lane >> 4;
    const int b_row_in    = (lane & 7) + ((lane >> 4) << 3);
    const int b_chunk_add = (lane >> 3) & 1;

    if (tid == 0) {
        MBAR_INIT(sb + MB_A, 1);
        MBAR_INIT(sb + MB_F0, 1);
        MBAR_INIT(sb + MB_F1, 1);
        MBAR_INIT(sb + MB_C0, 8);      // one arrival per warp (lane 0)
        MBAR_INIT(sb + MB_C1, 8);
    }
    __syncthreads();

    int rb = id0 >> 7;
    if (tid < 4) {
        if (tid == 0) MBAR_ARRIVE_TX(sb + MB_A, A_BLOCK);
        const uint8_t* srcA = g_an + (size_t)rb * A_BLOCK + tid * (A_BLOCK / 4);
        bulk_g2s(smA + tid * (A_BLOCK / 4), srcA, A_BLOCK / 4, sb + MB_A);
    }
    {
        int ct0 = id0 & 127;
        if (tid == 0) {
            MBAR_ARRIVE_TX(sb + MB_F0, B_BLOCK);
            bulk_g2s(sb + SM_B0, g_tn + (size_t)(ct0 * 2 + 0) * B_BLOCK, B_BLOCK, sb + MB_F0);
        }
        if (tid == 32) {
            MBAR_ARRIVE_TX(sb + MB_F1, B_BLOCK);
            bulk_g2s(sb + SM_B1, g_tn + (size_t)(ct0 * 2 + 1) * B_BLOCK, B_BLOCK, sb + MB_F1);
        }
    }
    int aph = 0;
    MBAR_WAIT(sb + MB_A, aph); aph ^= 1;

    float rs[4][2];
    #pragma unroll
    for (int i = 0; i < 4; ++i) { rs[i][0] = 0.f; rs[i][1] = 0.f; }

    int f0 = 0, f1 = 0, c0 = 0, c1 = 0;
    const int slot_base = (blockIdx.x & 7) * 2 + wn;   // 0..15

    for (int id = id0; id < id1; ++id) {
        const int nrb = id >> 7;
        if (nrb != rb) {
            #pragma unroll
            for (int i = 0; i < 4; ++i)
                #pragma unroll
                for (int hh = 0; hh < 2; ++hh) {
                    rs[i][hh] += __shfl_xor_sync(0xffffffffu, rs[i][hh], 1);
                    rs[i][hh] += __shfl_xor_sync(0xffffffffu, rs[i][hh], 2);
                }
            if ((lane & 3) == 0) {
                #pragma unroll
                for (int i = 0; i < 4; ++i) {
                    int r = rb * ROWS_CTA + wm * 64 + i * 16 + (lane >> 2);
                    g_ps[slot_base * BATCH + r]     = rs[i][0];
                    g_ps[slot_base * BATCH + r + 8] = rs[i][1];
                }
            }
            #pragma unroll
            for (int i = 0; i < 4; ++i) { rs[i][0] = 0.f; rs[i][1] = 0.f; }

            __syncthreads();
            rb = nrb;
            if (tid < 4) {
                if (tid == 0) MBAR_ARRIVE_TX(sb + MB_A, A_BLOCK);
                const uint8_t* srcA = g_an + (size_t)rb * A_BLOCK + tid * (A_BLOCK / 4);
                bulk_g2s(smA + tid * (A_BLOCK / 4), srcA, A_BLOCK / 4, sb + MB_A);
            }
            MBAR_WAIT(sb + MB_A, aph); aph ^= 1;
        }

        // two independent col-half chunks per tile; epilogue of chunk h overlaps
        // MMA of chunk h+1 (no shared accumulator, no convergence barrier between)
        #pragma unroll
        for (int h = 0; h < 2; ++h) {
            const uint32_t smB = sb + (h ? SM_B1 : SM_B0);
            if (h) { MBAR_WAIT(sb + MB_F1, f1); f1 ^= 1; }
            else   { MBAR_WAIT(sb + MB_F0, f0); f0 ^= 1; }

            float acc[4][4][4];
            #pragma unroll
            for (int i = 0; i < 4; ++i)
                #pragma unroll
                for (int j = 0; j < 4; ++j)
                    #pragma unroll
                    for (int c = 0; c < 4; ++c) acc[i][j][c] = 0.0f;

            #pragma unroll
            for (int step = 0; step < 16; ++step) {
                uint32_t af[4][4];
                #pragma unroll
                for (int i = 0; i < 4; ++i) {
                    int row = wm * 64 + i * 16 + a_row_in;
                    int chunk = step * 2 + a_chunk_add;
                    ldsm_x4(af[i], smA + row * A_STRIDE + (chunk << 4));
                }
                uint32_t bf[2][4];
                #pragma unroll
                for (int p = 0; p < 2; ++p) {
                    int row = wn * 32 + p * 16 + b_row_in;
                    int chunk = step * 2 + b_chunk_add;
                    ldsm_x4(bf[p], smB + row * B_STRIDE + (chunk << 4));
                }
                #pragma unroll
                for (int i = 0; i < 4; ++i)
                    #pragma unroll
                    for (int j = 0; j < 4; ++j)
                        mma16816(acc[i][j], af[i], &bf[j >> 1][(j & 1) * 2]);
            }

            if (h == 0) {
                if (lane == 0) MBAR_ARRIVE(sb + MB_C0);
                if (tid == 0 && id + 1 < id1) {
                    MBAR_WAIT(sb + MB_C0, c0); c0 ^= 1;
                    int nct = (id + 1) & 127;
                    MBAR_ARRIVE_TX(sb + MB_F0, B_BLOCK);
                    bulk_g2s(sb + SM_B0, g_tn + (size_t)(nct * 2 + 0) * B_BLOCK,
                             B_BLOCK, sb + MB_F0);
                }
            } else {
                if (lane == 0) MBAR_ARRIVE(sb + MB_C1);
                if (tid == 32 && id + 1 < id1) {
                    MBAR_WAIT(sb + MB_C1, c1); c1 ^= 1;
                    int nct = (id + 1) & 127;
                    MBAR_ARRIVE_TX(sb + MB_F1, B_BLOCK);
                    bulk_g2s(sb + SM_B1, g_tn + (size_t)(nct * 2 + 1) * B_BLOCK,
                             B_BLOCK, sb + MB_F1);
                }
            }

            // chunk epilogue: independent of the other chunk's MMA -> overlaps it
            #pragma unroll
            for (int i = 0; i < 4; ++i) {
                float s0 = 0.f, s1 = 0.f;
                #pragma unroll
                for (int j = 0; j < 4; ++j) {
                    s0 += ex2f(acc[i][j][0]) + ex2f(acc[i][j][1]);
                    s1 += ex2f(acc[i][j][2]) + ex2f(acc[i][j][3]);
                }
                rs[i][0] += s0;
                rs[i][1] += s1;
            }
        }
    }

    #pragma unroll
    for (int i = 0; i < 4; ++i)
        #pragma unroll
        for (int hh = 0; hh < 2; ++hh) {
            rs[i][hh] += __shfl_xor_sync(0xffffffffu, rs[i][hh], 1);
            rs[i][hh] += __shfl_xor_sync(0xffffffffu, rs[i][hh], 2);
        }
    if ((lane & 3) == 0) {
        #pragma unroll
        for (int i = 0; i < 4; ++i) {
            int r = rb * ROWS_CTA + wm * 64 + i * 16 + (lane >> 2);
            g_ps[slot_base * BATCH + r]     = rs[i][0];
            g_ps[slot_base * BATCH + r + 8] = rs[i][1];
        }
    }

    // ---- fused final reduction (device-wide sync; all 147 CTAs are one wave) ----
    __threadfence();
    __syncthreads();
    if (tid == 0) atomicAdd(&g_done, 1u);

    if (blockIdx.x < 32) {
        if (tid == 0) {
            while (atomicAdd(&g_done, 0u) < (unsigned)GRID_G) { }
        }
        __syncthreads();

        const int row = blockIdx.x * 256 + tid;
        float s = 0.0f;
        #pragma unroll
        for (int j = 0; j < 16; ++j) s += g_ps[j * BATCH + row];
        float v = log2f(s) - g_diag[row];

        __shared__ double sd[256];
        sd[tid] = (double)v;
        __syncthreads();
        #pragma unroll
        for (int k = 128; k > 0; k >>= 1) {
            if (tid < k) sd[tid] += sd[tid + k];
            __syncthreads();
        }
        if (tid == 0) {
            atomicAdd(&g_loss, sd[0]);
            __threadfence();
            unsigned t = atomicAdd(&g_tick, 1u);
            if (t == 31u) {
                double total = atomicAdd(&g_loss, 0.0);
                out[0] = (float)(total * LN2_D / (double)BATCH);
                g_loss = 0.0;
                g_tick = 0u;
                g_done = 0u;
                __threadfence();
            }
        }
    }
}

// ---------------- launcher ----------------
extern "C" void kernel_launch(void* const* d_in, const int* in_sizes, int n_in,
                              void* d_out, int out_size) {
    const float* A = (const float*)d_in[0];
    const float* P = (const float*)d_in[1];
    const float* N = (const float*)d_in[2];
    float* out = (float*)d_out;

    cudaFuncSetAttribute(k_gemm_lse, cudaFuncAttributeMaxDynamicSharedMemorySize,
                         SMEM_TOTAL);

    k_norm_diag<<<(2 * BATCH) / 8, 256>>>(A, P, N);
    k_gemm_lse<<<GRID_G, 256, SMEM_TOTAL>>>(out);
}

// round 16
// speedup vs baseline: 1.4861x; 1.0160x over previous
#include <cuda_runtime.h>
#include <cuda_bf16.h>
#include <cstdint>

// ---------------- problem constants ----------------
#define BATCH 8192
#define DIM   256
#define TGT   16384
#define ROWS_CTA 256
#define NRB   (BATCH / ROWS_CTA)          // 32 row-blocks
#define NCT   (TGT / 128)                 // 128 col-tiles
#define NWORK (NRB * NCT)                 // 4096 work units
#define WPC   28                          // tiles per CTA (contiguous)
#define GRID_G 147                        // one wave (148 resident CTAs max)
#define SCALE_A  28.8539008177792681f     // (1/0.05) * log2(e)
#define LN2_D    0.69314718055994530942

// Padded operand-image strides
#define A_STRIDE 528                       // 512 B data + 16 skew
#define B_STRIDE 528                       // 512 B data + 16 skew (full K per row)
#define A_BLOCK  (ROWS_CTA * A_STRIDE)     // 135168
#define B_BLOCK  (64 * B_STRIDE)           // 33792 per (tile, col-half)

// ---------------- scratch (device globals; pre-padded images) ----------------
__device__ __align__(1024) uint8_t g_an[NRB * A_BLOCK];
__device__ __align__(1024) uint8_t g_tn[NCT * 2 * B_BLOCK];
__device__ float  g_diag[BATCH];
__device__ float  g_ps[16 * BATCH];
__device__ double g_loss = 0.0;
__device__ unsigned g_tick = 0;
__device__ unsigned g_done = 0;

// ---------------- helpers ----------------
__device__ __forceinline__ uint32_t smem_u32(const void* p) {
    uint32_t a;
    asm("{ .reg .u64 t; cvta.to.shared.u64 t, %1; cvt.u32.u64 %0, t; }" : "=r"(a) : "l"(p));
    return a;
}
__device__ __forceinline__ float ex2f(float x) {
    float y; asm("ex2.approx.f32 %0, %1;" : "=f"(y) : "f"(x)); return y;
}
__device__ __forceinline__ uint2 bf16x4(float4 v, float s) {
    uint2 r;
    __nv_bfloat162 lo = __floats2bfloat162_rn(v.x * s, v.y * s);
    __nv_bfloat162 hi = __floats2bfloat162_rn(v.z * s, v.w * s);
    r.x = *(uint32_t*)&lo; r.y = *(uint32_t*)&hi;
    return r;
}
__device__ __forceinline__ void ldsm_x4(uint32_t* r, uint32_t addr) {
    asm volatile("ldmatrix.sync.aligned.m8n8.x4.shared.b16 {%0,%1,%2,%3}, [%4];"
        : "=r"(r[0]), "=r"(r[1]), "=r"(r[2]), "=r"(r[3]) : "r"(addr));
}
__device__ __forceinline__ void mma16816(float* d, const uint32_t* a, const uint32_t* b) {
    asm volatile("mma.sync.aligned.m16n8k16.row.col.f32.bf16.bf16.f32 "
        "{%0,%1,%2,%3}, {%4,%5,%6,%7}, {%8,%9}, {%0,%1,%2,%3};"
        : "+f"(d[0]), "+f"(d[1]), "+f"(d[2]), "+f"(d[3])
        : "r"(a[0]), "r"(a[1]), "r"(a[2]), "r"(a[3]), "r"(b[0]), "r"(b[1]));
}
__device__ __forceinline__ void bulk_g2s(uint32_t dst, const void* src,
                                         uint32_t bytes, uint32_t mbar) {
    asm volatile("cp.async.bulk.shared::cluster.global.mbarrier::complete_tx::bytes "
                 "[%0], [%1], %2, [%3];"
                 :: "r"(dst), "l"(src), "r"(bytes), "r"(mbar) : "memory");
}
#define MBAR_INIT(a, c) asm volatile("mbarrier.init.shared.b64 [%0], %1;" :: "r"(a), "r"((uint32_t)(c)) : "memory")
#define MBAR_ARRIVE(a)  asm volatile("mbarrier.arrive.shared.b64 _, [%0];" :: "r"(a) : "memory")
#define MBAR_ARRIVE_TX(a, tx) asm volatile("mbarrier.arrive.expect_tx.shared.b64 _, [%0], %1;" :: "r"(a), "r"((uint32_t)(tx)) : "memory")
#define MBAR_WAIT(addr, parity) do {                                              \
    uint32_t _m = (addr); uint32_t _p = (parity); uint32_t _d;                    \
    asm volatile("{ .reg .pred p;\n\t"                                            \
        "mbarrier.try_wait.parity.acquire.cta.shared::cta.b64 p, [%1], %2;\n\t"   \
        "selp.b32 %0, 1, 0, p; }" : "=r"(_d) : "r"(_m), "r"(_p) : "memory");      \
    if (!_d) {                                                                    \
        asm volatile("{ .reg .pred P1;\n\t"                                       \
            "WL_%=:\n\t"                                                          \
            "mbarrier.try_wait.parity.acquire.cta.shared::cta.b64 P1, [%0], %1, 0x989680;\n\t" \
            "@P1 bra.uni WD_%=;\n\t"                                              \
            "bra.uni WL_%=;\n\t"                                                  \
            "WD_%=: }" :: "r"(_m), "r"(_p) : "memory");                           \
    }                                                                             \
} while (0)

// producer wait: post-wait accesses are async-proxy only (cp.async.bulk) -> relaxed OK
#define MBAR_WAIT_RELAXED(addr, parity) do {                                      \
    uint32_t _m = (addr); uint32_t _p = (parity); uint32_t _d;                    \
    asm volatile("{ .reg .pred p;\n\t"                                            \
        "mbarrier.try_wait.parity.relaxed.cta.shared::cta.b64 p, [%1], %2, 0x989680;\n\t" \
        "selp.b32 %0, 1, 0, p; }" : "=r"(_d) : "r"(_m), "r"(_p) : "memory");      \
    if (!_d) {                                                                    \
        asm volatile("{ .reg .pred P1;\n\t"                                       \
            "WL_%=:\n\t"                                                          \
            "mbarrier.try_wait.parity.relaxed.cta.shared::cta.b64 P1, [%0], %1, 0x989680;\n\t" \
            "@P1 bra.uni WD_%=;\n\t"                                              \
            "bra.uni WL_%=;\n\t"                                                  \
            "WD_%=: }" :: "r"(_m), "r"(_p) : "memory");                           \
    }                                                                             \
} while (0)

// -------- kernel 1: fused normalize (bf16, padded images) + exact diag + zero g_ps --------
__global__ void k_norm_diag(const float* __restrict__ A,
                            const float* __restrict__ P,
                            const float* __restrict__ N) {
    if (blockIdx.x < 512) {
        g_ps[blockIdx.x * 256 + threadIdx.x] = 0.0f;
    }
    int gw   = (blockIdx.x * blockDim.x + threadIdx.x) >> 5;
    int lane = threadIdx.x & 31;
    if (gw >= 2 * BATCH) return;

    if (gw < BATCH) {
        const float* a = A + (size_t)gw * DIM;
        const float* p = P + (size_t)gw * DIM;
        float4 a0 = ((const float4*)a)[lane], a1 = ((const float4*)a)[lane + 32];
        float4 p0 = ((const float4*)p)[lane], p1 = ((const float4*)p)[lane + 32];
        float saa = a0.x*a0.x + a0.y*a0.y + a0.z*a0.z + a0.w*a0.w
                  + a1.x*a1.x + a1.y*a1.y + a1.z*a1.z + a1.w*a1.w;
        float spp = p0.x*p0.x + p0.y*p0.y + p0.z*p0.z + p0.w*p0.w
                  + p1.x*p1.x + p1.y*p1.y + p1.z*p1.z + p1.w*p1.w;
        float sap = a0.x*p0.x + a0.y*p0.y + a0.z*p0.z + a0.w*p0.w
                  + a1.x*p1.x + a1.y*p1.y + a1.z*p1.z + a1.w*p1.w;
        #pragma unroll
        for (int o = 16; o; o >>= 1) {
            saa += __shfl_xor_sync(0xffffffffu, saa, o);
            spp += __shfl_xor_sync(0xffffffffu, spp, o);
            sap += __shfl_xor_sync(0xffffffffu, sap, o);
        }
        float na = fmaxf(sqrtf(saa), 1e-12f);
        float np = fmaxf(sqrtf(spp), 1e-12f);
        float ia = SCALE_A / na;
        float ip = 1.0f / np;
        {
            int R = gw >> 8, r = gw & 255;
            uint8_t* base = g_an + (size_t)R * A_BLOCK + (size_t)r * A_STRIDE;
            *(uint2*)(base + 8 * lane)       = bf16x4(a0, ia);
            *(uint2*)(base + 256 + 8 * lane) = bf16x4(a1, ia);
        }
        {
            int T = gw >> 7, h = (gw >> 6) & 1, r2 = gw & 63;
            uint8_t* b = g_tn + (size_t)(T * 2 + h) * B_BLOCK + (size_t)r2 * B_STRIDE;
            *(uint2*)(b + 8 * lane)       = bf16x4(p0, ip);
            *(uint2*)(b + 256 + 8 * lane) = bf16x4(p1, ip);
        }
        if (lane == 0) g_diag[gw] = sap / (na * np) * SCALE_A;
    } else {
        int j = gw - BATCH;
        const float* n = N + (size_t)j * DIM;
        float4 n0 = ((const float4*)n)[lane], n1 = ((const float4*)n)[lane + 32];
        float s = n0.x*n0.x + n0.y*n0.y + n0.z*n0.z + n0.w*n0.w
                + n1.x*n1.x + n1.y*n1.y + n1.z*n1.z + n1.w*n1.w;
        #pragma unroll
        for (int o = 16; o; o >>= 1) s += __shfl_xor_sync(0xffffffffu, s, o);
        float inv = 1.0f / fmaxf(sqrtf(s), 1e-12f);
        int c = BATCH + j;
        int T = c >> 7, h = (c >> 6) & 1, r2 = c & 63;
        uint8_t* b = g_tn + (size_t)(T * 2 + h) * B_BLOCK + (size_t)r2 * B_STRIDE;
        *(uint2*)(b + 8 * lane)       = bf16x4(n0, inv);
        *(uint2*)(b + 256 + 8 * lane) = bf16x4(n1, inv);
    }
}

// ---------------- SMEM layout ----------------
#define SM_A   0
#define SM_B0  A_BLOCK
#define SM_B1  (SM_B0 + B_BLOCK)
#define MB_A   (SM_B1 + B_BLOCK)
#define MB_F0  (MB_A + 8)
#define MB_F1  (MB_A + 16)
#define MB_C0  (MB_A + 24)
#define MB_C1  (MB_A + 32)
#define SMEM_TOTAL (MB_A + 64)

// ---------------- kernel 2: persistent bf16 mma GEMM + sum-exp2 + fused reduction ----------------
// 256 threads = 8 warps as 4(M) x 2(N); per col-half warp tile 64x32; CTA tile 256x128.
__global__ void __launch_bounds__(256, 1) k_gemm_lse(float* __restrict__ out) {
    extern __shared__ __align__(128) char smem[];
    const uint32_t sb  = smem_u32(smem);
    const uint32_t smA = sb + SM_A;

    const int tid  = threadIdx.x;
    const int lane = tid & 31;
    const int wid  = tid >> 5;
    const int wm   = wid & 3;     // 4 M-warps (64 rows)
    const int wn   = wid >> 2;    // 2 N-warps (32 cols within each 64-col half)

    const int id0 = blockIdx.x * WPC;
    const int id1 = (id0 + WPC < NWORK) ? id0 + WPC : NWORK;

    const int a_row_in    = lane & 15;
    const int a_chunk_add = lane >> 4;
    const int b_row_in    = (lane & 7) + ((lane >> 4) << 3);
    const int b_chunk_add = (lane >> 3) & 1;

    if (tid == 0) {
        MBAR_INIT(sb + MB_A, 1);
        MBAR_INIT(sb + MB_F0, 1);
        MBAR_INIT(sb + MB_F1, 1);
        MBAR_INIT(sb + MB_C0, 256);
        MBAR_INIT(sb + MB_C1, 256);
    }
    __syncthreads();

    int rb = id0 >> 7;
    if (tid < 4) {
        if (tid == 0) MBAR_ARRIVE_TX(sb + MB_A, A_BLOCK);
        const uint8_t* srcA = g_an + (size_t)rb * A_BLOCK + tid * (A_BLOCK / 4);
        bulk_g2s(smA + tid * (A_BLOCK / 4), srcA, A_BLOCK / 4, sb + MB_A);
    }
    {
        int ct0 = id0 & 127;
        if (tid == 0) {
            MBAR_ARRIVE_TX(sb + MB_F0, B_BLOCK);
            bulk_g2s(sb + SM_B0, g_tn + (size_t)(ct0 * 2 + 0) * B_BLOCK, B_BLOCK, sb + MB_F0);
        }
        if (tid == 32) {
            MBAR_ARRIVE_TX(sb + MB_F1, B_BLOCK);
            bulk_g2s(sb + SM_B1, g_tn + (size_t)(ct0 * 2 + 1) * B_BLOCK, B_BLOCK, sb + MB_F1);
        }
    }
    int aph = 0;
    MBAR_WAIT(sb + MB_A, aph); aph ^= 1;

    float rs[4][2];
    #pragma unroll
    for (int i = 0; i < 4; ++i) { rs[i][0] = 0.f; rs[i][1] = 0.f; }

    int f0 = 0, f1 = 0, c0 = 0, c1 = 0;
    const int slot_base = (blockIdx.x & 7) * 2 + wn;   // 0..15

    for (int id = id0; id < id1; ++id) {
        const int nrb = id >> 7;
        if (nrb != rb) {
            #pragma unroll
            for (int i = 0; i < 4; ++i)
                #pragma unroll
                for (int hh = 0; hh < 2; ++hh) {
                    rs[i][hh] += __shfl_xor_sync(0xffffffffu, rs[i][hh], 1);
                    rs[i][hh] += __shfl_xor_sync(0xffffffffu, rs[i][hh], 2);
                }
            if ((lane & 3) == 0) {
                #pragma unroll
                for (int i = 0; i < 4; ++i) {
                    int r = rb * ROWS_CTA + wm * 64 + i * 16 + (lane >> 2);
                    g_ps[slot_base * BATCH + r]     = rs[i][0];
                    g_ps[slot_base * BATCH + r + 8] = rs[i][1];
                }
            }
            #pragma unroll
            for (int i = 0; i < 4; ++i) { rs[i][0] = 0.f; rs[i][1] = 0.f; }

            __syncthreads();
            rb = nrb;
            if (tid < 4) {
                if (tid == 0) MBAR_ARRIVE_TX(sb + MB_A, A_BLOCK);
                const uint8_t* srcA = g_an + (size_t)rb * A_BLOCK + tid * (A_BLOCK / 4);
                bulk_g2s(smA + tid * (A_BLOCK / 4), srcA, A_BLOCK / 4, sb + MB_A);
            }
            MBAR_WAIT(sb + MB_A, aph); aph ^= 1;
        }

        // two independent col-half chunks per tile; epilogue of chunk h overlaps
        // MMA of chunk h+1 (no shared accumulator, no convergence barrier between)
        #pragma unroll
        for (int h = 0; h < 2; ++h) {
            const uint32_t smB = sb + (h ? SM_B1 : SM_B0);
            if (h) { MBAR_WAIT(sb + MB_F1, f1); f1 ^= 1; }
            else   { MBAR_WAIT(sb + MB_F0, f0); f0 ^= 1; }

            float acc[4][4][4];
            #pragma unroll
            for (int i = 0; i < 4; ++i)
                #pragma unroll
                for (int j = 0; j < 4; ++j)
                    #pragma unroll
                    for (int c = 0; c < 4; ++c) acc[i][j][c] = 0.0f;

            #pragma unroll
            for (int step = 0; step < 16; ++step) {
                uint32_t af[4][4];
                #pragma unroll
                for (int i = 0; i < 4; ++i) {
                    int row = wm * 64 + i * 16 + a_row_in;
                    int chunk = step * 2 + a_chunk_add;
                    ldsm_x4(af[i], smA + row * A_STRIDE + (chunk << 4));
                }
                uint32_t bf[2][4];
                #pragma unroll
                for (int p = 0; p < 2; ++p) {
                    int row = wn * 32 + p * 16 + b_row_in;
                    int chunk = step * 2 + b_chunk_add;
                    ldsm_x4(bf[p], smB + row * B_STRIDE + (chunk << 4));
                }
                #pragma unroll
                for (int i = 0; i < 4; ++i)
                    #pragma unroll
                    for (int j = 0; j < 4; ++j)
                        mma16816(acc[i][j], af[i], &bf[j >> 1][(j & 1) * 2]);
            }

            if (h == 0) {
                MBAR_ARRIVE(sb + MB_C0);
                if (tid == 0 && id + 1 < id1) {
                    MBAR_WAIT_RELAXED(sb + MB_C0, c0); c0 ^= 1;
                    int nct = (id + 1) & 127;
                    MBAR_ARRIVE_TX(sb + MB_F0, B_BLOCK);
                    bulk_g2s(sb + SM_B0, g_tn + (size_t)(nct * 2 + 0) * B_BLOCK,
                             B_BLOCK, sb + MB_F0);
                }
            } else {
                MBAR_ARRIVE(sb + MB_C1);
                if (tid == 32 && id + 1 < id1) {
                    MBAR_WAIT_RELAXED(sb + MB_C1, c1); c1 ^= 1;
                    int nct = (id + 1) & 127;
                    MBAR_ARRIVE_TX(sb + MB_F1, B_BLOCK);
                    bulk_g2s(sb + SM_B1, g_tn + (size_t)(nct * 2 + 1) * B_BLOCK,
                             B_BLOCK, sb + MB_F1);
                }
            }

            // chunk epilogue: independent of the other chunk's MMA -> overlaps it
            #pragma unroll
            for (int i = 0; i < 4; ++i) {
                float s0 = 0.f, s1 = 0.f;
                #pragma unroll
                for (int j = 0; j < 4; ++j) {
                    s0 += ex2f(acc[i][j][0]) + ex2f(acc[i][j][1]);
                    s1 += ex2f(acc[i][j][2]) + ex2f(acc[i][j][3]);
                }
                rs[i][0] += s0;
                rs[i][1] += s1;
            }
        }
    }

    #pragma unroll
    for (int i = 0; i < 4; ++i)
        #pragma unroll
        for (int hh = 0; hh < 2; ++hh) {
            rs[i][hh] += __shfl_xor_sync(0xffffffffu, rs[i][hh], 1);
            rs[i][hh] += __shfl_xor_sync(0xffffffffu, rs[i][hh], 2);
        }
    if ((lane & 3) == 0) {
        #pragma unroll
        for (int i = 0; i < 4; ++i) {
            int r = rb * ROWS_CTA + wm * 64 + i * 16 + (lane >> 2);
            g_ps[slot_base * BATCH + r]     = rs[i][0];
            g_ps[slot_base * BATCH + r + 8] = rs[i][1];
        }
    }

    // ---- fused final reduction (device-wide sync; all 147 CTAs are one wave) ----
    __threadfence();
    __syncthreads();
    if (tid == 0) atomicAdd(&g_done, 1u);

    if (blockIdx.x < 32) {
        if (tid == 0) {
            while (atomicAdd(&g_done, 0u) < (unsigned)GRID_G) { }
        }
        __syncthreads();

        const int row = blockIdx.x * 256 + tid;
        float s = 0.0f;
        #pragma unroll
        for (int j = 0; j < 16; ++j) s += g_ps[j * BATCH + row];
        float v = log2f(s) - g_diag[row];

        __shared__ double sd[256];
        sd[tid] = (double)v;
        __syncthreads();
        #pragma unroll
        for (int k = 128; k > 0; k >>= 1) {
            if (tid < k) sd[tid] += sd[tid + k];
            __syncthreads();
        }
        if (tid == 0) {
            atomicAdd(&g_loss, sd[0]);
            __threadfence();
            unsigned t = atomicAdd(&g_tick, 1u);
            if (t == 31u) {
                double total = atomicAdd(&g_loss, 0.0);
                out[0] = (float)(total * LN2_D / (double)BATCH);
                g_loss = 0.0;
                g_tick = 0u;
                g_done = 0u;
                __threadfence();
            }
        }
    }
}

// ---------------- launcher ----------------
extern "C" void kernel_launch(void* const* d_in, const int* in_sizes, int n_in,
                              void* d_out, int out_size) {
    const float* A = (const float*)d_in[0];
    const float* P = (const float*)d_in[1];
    const float* N = (const float*)d_in[2];
    float* out = (float*)d_out;

    cudaFuncSetAttribute(k_gemm_lse, cudaFuncAttributeMaxDynamicSharedMemorySize,
                         SMEM_TOTAL);

    k_norm_diag<<<(2 * BATCH) / 8, 256>>>(A, P, N);
    k_gemm_lse<<<GRID_G, 256, SMEM_TOTAL>>>(out);
}